// round 12
// baseline (speedup 1.0000x reference)
#include <cuda_runtime.h>
#include <cstdint>
#include <math.h>

// NeuralODE, persistent-kernel version. mma.sync m16n8k8 tf32, cp.async ring,
// fragment-native layouts (verified R7-R11).
// h_{n+1} = h_n + 0.1 * tanh(h_n @ W[k]^T + b[k]), k = n/10, n = 0..99, B=D=1024.
// R12: ONE kernel runs all 100 steps; 256 CTAs (= exactly 2/SM on 148 SMs, all
// co-resident) synchronize between steps via atomic grid barrier. Next step's
// W tiles are cp.async-prefetched across the barrier; exchange buffer lives in
// ring slot 2 so slots 0/1 are free for the prefetch.

#define D_DIM   1024
#define BM      64
#define BN      64
#define THREADS 256
#define KITERS  16
#define STAGES  3
#define GRID_CTAS 256
#define NSTEPS  100

#define A_WORDS 4096                 // 64 rows x 64 k
#define B_WORDS 4096                 // 64 n x 64 k
#define STAGE_WORDS (A_WORDS + B_WORDS)   // 8192
#define SMEM_BYTES (STAGES * STAGE_WORDS * 4)  // 98304

__device__ uint32_t g_Wtf[10u * 1024u * 1024u];   // W tf32, k16-fused B-block layout
__device__ uint32_t g_Htf[2][1024u * 1024u];      // H tf32 ping-pong, A-block layout
__device__ int g_arrive[128];                     // grid-barrier counters (memset per launch)

__device__ __forceinline__ uint32_t f2tf32(float f) {
    uint32_t r;
    asm("cvt.rna.tf32.f32 %0, %1;" : "=r"(r) : "f"(f));
    return r;
}

__device__ __forceinline__ void mma_tf32(float c[4],
                                         uint32_t a0, uint32_t a1,
                                         uint32_t a2, uint32_t a3,
                                         uint32_t b0, uint32_t b1) {
    asm volatile(
        "mma.sync.aligned.m16n8k8.row.col.f32.tf32.tf32.f32 "
        "{%0,%1,%2,%3}, {%4,%5,%6,%7}, {%8,%9}, {%0,%1,%2,%3};"
        : "+f"(c[0]), "+f"(c[1]), "+f"(c[2]), "+f"(c[3])
        : "r"(a0), "r"(a1), "r"(a2), "r"(a3), "r"(b0), "r"(b1));
}

__device__ __forceinline__ float fast_tanh(float x) {
    float ax = fabsf(x);
    float t = __expf(-2.0f * ax);
    float r = __fdividef(1.0f - t, 1.0f + t);
    return copysignf(r, x);
}

__device__ __forceinline__ uint32_t smem_u32(const void* p) {
    uint32_t a;
    asm("{ .reg .u64 t; cvta.to.shared.u64 t, %1; cvt.u32.u64 %0, t; }"
        : "=r"(a) : "l"(p));
    return a;
}

#define CP_ASYNC(dst, src) \
    asm volatile("cp.async.cg.shared.global [%0], [%1], 16;" \
                 :: "r"(dst), "l"(src) : "memory")
#define CP_COMMIT() asm volatile("cp.async.commit_group;" ::: "memory")
#define CP_WAIT1()  asm volatile("cp.async.wait_group 1;" ::: "memory")

// ---- W convert: k16-fused B-block layout (verified R11) ----
__global__ void convert_W(const float* __restrict__ W, uint32_t* __restrict__ out)
{
    const int nquads = 10 * 1024 * 1024 / 4;
    for (int q = blockIdx.x * blockDim.x + threadIdx.x; q < nquads;
         q += gridDim.x * blockDim.x) {
        uint32_t blk  = (uint32_t)q >> 5;
        uint32_t lane = (uint32_t)q & 31;
        uint32_t slab = blk >> 13;
        uint32_t rem  = blk & 8191u;
        uint32_t nb = rem >> 6, kp = rem & 63u;
        uint32_t g = lane >> 2, tig = lane & 3;
        const float* s = W + (size_t)slab * 1048576u
                           + (size_t)(nb * 8 + g) * 1024u + kp * 16 + tig;
        uint4 v;
        v.x = f2tf32(s[0]);
        v.y = f2tf32(s[4]);
        v.z = f2tf32(s[8]);
        v.w = f2tf32(s[12]);
        *reinterpret_cast<uint4*>(out + (size_t)q * 4) = v;
    }
}

// ---- X convert: A-block layout (verified R7-R11) ----
__global__ void convert_X(const float* __restrict__ x, uint32_t* __restrict__ out)
{
    const int nquads = 1024 * 1024 / 4;
    for (int q = blockIdx.x * blockDim.x + threadIdx.x; q < nquads;
         q += gridDim.x * blockDim.x) {
        uint32_t blk  = (uint32_t)q >> 5;
        uint32_t lane = (uint32_t)q & 31;
        uint32_t rb = blk >> 7, kb = blk & 127u;
        uint32_t g = lane >> 2, tig = lane & 3;
        const float* s0 = x + (size_t)(rb * 16 + g) * 1024u + kb * 8 + tig;
        uint4 v;
        v.x = f2tf32(s0[0]);
        v.y = f2tf32(s0[8192]);
        v.z = f2tf32(s0[4]);
        v.w = f2tf32(s0[8192 + 4]);
        *reinterpret_cast<uint4*>(out + (size_t)q * 4) = v;
    }
}

__global__ __launch_bounds__(THREADS, 2)
void ode_all(const uint32_t* __restrict__ Wtf,    // all 10 slabs, k16-fused layout
             const float*    __restrict__ bias,   // [10, 1024]
             uint32_t* __restrict__ htf0,
             uint32_t* __restrict__ htf1,
             float*    __restrict__ traj)         // [101, 1024, 1024]
{
    extern __shared__ uint32_t smem[];
    const uint32_t sbase = smem_u32(smem);
    const size_t BD = (size_t)D_DIM * D_DIM;

    const int tid  = threadIdx.x;
    const int wid  = tid >> 5;
    const int lane = tid & 31;
    const int g    = lane >> 2;
    const int tig  = lane & 3;
    const int wm   = wid & 1;
    const int wn   = (wid >> 1) & 1;
    const int ks   = wid >> 2;
    const int bm   = blockIdx.y * BM;
    const int bn   = blockIdx.x * BN;
    const int rb0  = blockIdx.y * 4;
    const int nb0  = blockIdx.x * 8;

    auto issueA = [&](const uint32_t* __restrict__ Atf, int s, int slot) {
        const uint32_t sst = sbase + (uint32_t)(slot * STAGE_WORDS) * 4u;
        const int kb0 = s * 8;
#pragma unroll
        for (int i = 0; i < 4; i++) {
            int c = tid + i * THREADS;
            int rbl = c >> 8, j = c & 255;
            const uint32_t* src = Atf + ((size_t)(rb0 + rbl) * 128 + kb0) * 128 + j * 4;
            CP_ASYNC(sst + (uint32_t)(rbl * 1024 + j * 4) * 4u, src);
        }
    };
    auto issueB = [&](const uint32_t* __restrict__ Btf, int s, int slot) {
        const uint32_t sst = sbase + (uint32_t)(slot * STAGE_WORDS) * 4u;
        const int kp0 = s * 4;
#pragma unroll
        for (int i = 0; i < 4; i++) {
            int c = tid + i * THREADS;
            int nbl = c >> 7, j = c & 127;
            const uint32_t* src = Btf + ((size_t)(nb0 + nbl) * 64 + kp0) * 128 + j * 4;
            CP_ASYNC(sst + (uint32_t)(A_WORDS + nbl * 512 + j * 4) * 4u, src);
        }
    };

    uint32_t fa[2][2][4];
    uint4    fbp[2][4];
    float    acc[2][4][4];

    auto loadA = [&](const uint32_t* __restrict__ st, int j, int p) {
#pragma unroll
        for (int mt = 0; mt < 2; mt++) {
            uint4 v = *reinterpret_cast<const uint4*>(
                st + ((wm * 2 + mt) * 8 + j) * 128 + lane * 4);
            fa[p][mt][0] = v.x; fa[p][mt][1] = v.y;
            fa[p][mt][2] = v.z; fa[p][mt][3] = v.w;
        }
    };
    auto loadBpair = [&](const uint32_t* __restrict__ st, int kpl, int pr) {
#pragma unroll
        for (int nt = 0; nt < 4; nt++) {
            fbp[pr][nt] = *reinterpret_cast<const uint4*>(
                st + A_WORDS + ((wn * 4 + nt) * 4 + kpl) * 128 + lane * 4);
        }
    };
    auto do_mma = [&](int p, int pr, int odd) {
#pragma unroll
        for (int mt = 0; mt < 2; mt++)
#pragma unroll
            for (int nt = 0; nt < 4; nt++) {
                uint32_t b0 = odd ? fbp[pr][nt].z : fbp[pr][nt].x;
                uint32_t b1 = odd ? fbp[pr][nt].w : fbp[pr][nt].y;
                mma_tf32(acc[mt][nt],
                         fa[p][mt][0], fa[p][mt][1], fa[p][mt][2], fa[p][mt][3],
                         b0, b1);
            }
    };

    const int jb  = ks * 4;
    const int kpb = ks * 2;

    // prefetch step-0 W tiles for stages 0,1 (uncommitted; joins group g0/g1 below)
    issueB(Wtf, 0, 0);
    issueB(Wtf, 1, 1);

    for (int n = 0; n < NSTEPS; n++) {
        const uint32_t* Atf    = (n & 1) ? htf1 : htf0;
        uint32_t*       Houttf = (n & 1) ? htf0 : htf1;
        const uint32_t* Btf    = Wtf + (size_t)(n / 10) * BD;
        const float*    bk     = bias + (size_t)(n / 10) * D_DIM;
        const float*    Hfp    = traj + (size_t)n * BD;
        float*          Hout   = traj + (size_t)(n + 1) * BD;

        // complete the 2-stage fill: A halves (B halves already inflight)
        issueA(Atf, 0, 0); CP_COMMIT();     // g: {B0, B1(prefetched), A0} ... B1 joins g0 too;
        issueA(Atf, 1, 1); CP_COMMIT();     // both B prefetches complete within g0 -> safe.

#pragma unroll
        for (int mt = 0; mt < 2; mt++)
#pragma unroll
            for (int nt = 0; nt < 4; nt++)
#pragma unroll
                for (int r = 0; r < 4; r++) acc[mt][nt][r] = 0.0f;

        int slot = 0, nslot = 2;
        for (int s = 0; s < KITERS; s++) {
            CP_WAIT1();
            __syncthreads();

            const uint32_t* st = smem + slot * STAGE_WORDS;

            loadA(st, jb + 0, 0);
            loadBpair(st, kpb + 0, 0);

            if (s + 2 < KITERS) {
                issueA(Atf, s + 2, nslot);
                issueB(Btf, s + 2, nslot);
            }
            CP_COMMIT();

            loadA(st, jb + 1, 1);
            do_mma(0, 0, 0);
            loadA(st, jb + 2, 0);
            loadBpair(st, kpb + 1, 1);
            do_mma(1, 0, 1);
            loadA(st, jb + 3, 1);
            do_mma(0, 1, 0);
            do_mma(1, 1, 1);

            slot = slot + 1 == STAGES ? 0 : slot + 1;
            nslot = nslot + 1 == STAGES ? 0 : nslot + 1;
        }

        __syncthreads();   // all warps done reading all ring slots

        // prefetch NEXT step's W tiles into slots 0,1 (uncommitted across barrier)
        if (n + 1 < NSTEPS) {
            const uint32_t* BtfN = Wtf + (size_t)((n + 1) / 10) * BD;
            issueB(BtfN, 0, 0);
            issueB(BtfN, 1, 1);
        }

        // ---- k-split reduction in ring slot 2 (disjoint from prefetch slots) ----
        float* ex = reinterpret_cast<float*>(smem + 2 * STAGE_WORDS);
        const int p = wid & 3;
        if (ks == 0) {
#pragma unroll
            for (int mt = 0; mt < 2; mt++)
#pragma unroll
                for (int nh = 0; nh < 2; nh++) {
                    int q = mt * 2 + nh;
                    float4 v = { acc[mt][2 + nh][0], acc[mt][2 + nh][1],
                                 acc[mt][2 + nh][2], acc[mt][2 + nh][3] };
                    *reinterpret_cast<float4*>(ex + (p * 4 + q) * 128 + lane * 4) = v;
                }
        } else {
#pragma unroll
            for (int mt = 0; mt < 2; mt++)
#pragma unroll
                for (int nh = 0; nh < 2; nh++) {
                    int q = mt * 2 + nh;
                    float4 v = { acc[mt][nh][0], acc[mt][nh][1],
                                 acc[mt][nh][2], acc[mt][nh][3] };
                    *reinterpret_cast<float4*>(ex + 2048 + (p * 4 + q) * 128 + lane * 4) = v;
                }
        }
        __syncthreads();
        const int ntb = ks ? 2 : 0;
        const int exo = ks ? 0 : 2048;
#pragma unroll
        for (int mt = 0; mt < 2; mt++)
#pragma unroll
            for (int nh = 0; nh < 2; nh++) {
                int q = mt * 2 + nh;
                float4 v = *reinterpret_cast<const float4*>(
                    ex + exo + (p * 4 + q) * 128 + lane * 4);
                acc[mt][ntb + nh][0] += v.x;
                acc[mt][ntb + nh][1] += v.y;
                acc[mt][ntb + nh][2] += v.z;
                acc[mt][ntb + nh][3] += v.w;
            }

        // ---- fused epilogue (verified R7-R11) ----
#pragma unroll
        for (int mt = 0; mt < 2; mt++) {
#pragma unroll
            for (int nh = 0; nh < 2; nh++) {
                const int nt = ntb + nh;
                const int R = bm + wm * 32 + mt * 16 + g;
                const int C = bn + wn * 32 + nt * 8 + tig * 2;
                const float b0 = __ldg(&bk[C]);
                const float b1 = __ldg(&bk[C + 1]);

                float2 h0 = *reinterpret_cast<const float2*>(&Hfp[(size_t)R * D_DIM + C]);
                float2 h1 = *reinterpret_cast<const float2*>(&Hfp[(size_t)(R + 8) * D_DIM + C]);
                float o0 = h0.x + 0.1f * fast_tanh(acc[mt][nt][0] + b0);
                float o1 = h0.y + 0.1f * fast_tanh(acc[mt][nt][1] + b1);
                float o2 = h1.x + 0.1f * fast_tanh(acc[mt][nt][2] + b0);
                float o3 = h1.y + 0.1f * fast_tanh(acc[mt][nt][3] + b1);
                *reinterpret_cast<float2*>(&Hout[(size_t)R * D_DIM + C]) = make_float2(o0, o1);
                *reinterpret_cast<float2*>(&Hout[(size_t)(R + 8) * D_DIM + C]) = make_float2(o2, o3);

                const int rb = R >> 4, kb = C >> 3;
                const int t2 = tig * 2;
                const int kw = t2 >> 2;
                const int lane0 = g * 4 + (t2 & 3);
                const int lane1 = g * 4 + ((t2 + 1) & 3);
                uint32_t* base = Houttf + ((size_t)rb * 128 + kb) * 128 + 2 * kw;
                uint2 u02 = { f2tf32(o0), f2tf32(o2) };
                uint2 u13 = { f2tf32(o1), f2tf32(o3) };
                *reinterpret_cast<uint2*>(base + lane0 * 4) = u02;
                *reinterpret_cast<uint2*>(base + lane1 * 4) = u13;
            }
        }

        // ---- grid barrier between steps ----
        if (n + 1 < NSTEPS) {
            __threadfence();              // publish Hout/Houttf
            __syncthreads();              // whole CTA fenced
            if (tid == 0) {
                atomicAdd(&g_arrive[n], 1);
                volatile int* ctr = &g_arrive[n];
                while (*ctr < GRID_CTAS) __nanosleep(64);
            }
            __syncthreads();              // release whole CTA
        }
    }
}

extern "C" void kernel_launch(void* const* d_in, const int* in_sizes, int n_in,
                              void* d_out, int out_size)
{
    (void)in_sizes; (void)n_in; (void)out_size;
    const float* x = (const float*)d_in[0];   // [1024, 1024]
    const float* W = (const float*)d_in[1];   // [10, 1024, 1024]
    const float* b = (const float*)d_in[2];   // [10, 1024]

    float* out  = (float*)d_out;
    const size_t BD = (size_t)D_DIM * D_DIM;
    float* feat = out;
    float* traj = out + BD;

    uint32_t *wtf = nullptr, *htf = nullptr;
    int* arrive = nullptr;
    cudaGetSymbolAddress((void**)&wtf, g_Wtf);
    cudaGetSymbolAddress((void**)&htf, g_Htf);
    cudaGetSymbolAddress((void**)&arrive, g_arrive);
    uint32_t* htf0 = htf;
    uint32_t* htf1 = htf + BD;

    cudaFuncSetAttribute(ode_all,
                         cudaFuncAttributeMaxDynamicSharedMemorySize, SMEM_BYTES);

    cudaMemsetAsync(arrive, 0, 128 * sizeof(int), 0);
    convert_W<<<4096, 256>>>(W, wtf);
    convert_X<<<1024, 256>>>(x, htf0);
    cudaMemcpyAsync(traj, x, BD * sizeof(float), cudaMemcpyDeviceToDevice, 0);

    dim3 grid(D_DIM / BN, D_DIM / BM);   // (16, 16) = 256 CTAs, all co-resident
    dim3 block(THREADS);
    ode_all<<<grid, block, SMEM_BYTES, 0>>>(wtf, b, htf0, htf1, traj);

    cudaMemcpyAsync(feat, traj + (size_t)100 * BD, BD * sizeof(float),
                    cudaMemcpyDeviceToDevice, 0);
}

// round 13
// speedup vs baseline: 1.0006x; 1.0006x over previous
#include <cuda_runtime.h>
#include <cstdint>
#include <math.h>

// NeuralODE via mma.sync m16n8k8 tf32. R13: A operand streams DIRECTLY from
// global (fragment-block layout -> coalesced LDG.128 into a depth-4 register
// ring), B via 3-stage cp.async smem ring. Halves smem-crossbar traffic vs R11.
// h_{n+1} = h_n + 0.1 * tanh(h_n @ W[k]^T + b[k]), k = n/10, n = 0..99, B=D=1024.
// CTA 64x64, 256 thr (2m x 2n x 2k), 2 CTAs/SM, grid (16,16)=256.

#define D_DIM   1024
#define BM      64
#define BN      64
#define THREADS 256
#define KITERS  16
#define STAGES  3

#define B_WORDS 4096                 // 64 n x 64 k per stage
#define SMEM_BYTES (STAGES * B_WORDS * 4)   // 49152

__device__ uint32_t g_Wtf[10u * 1024u * 1024u];   // W tf32, k16-fused B-block layout
__device__ uint32_t g_Htf[2][1024u * 1024u];      // H tf32 ping-pong, A-block layout

__device__ __forceinline__ uint32_t f2tf32(float f) {
    uint32_t r;
    asm("cvt.rna.tf32.f32 %0, %1;" : "=r"(r) : "f"(f));
    return r;
}

__device__ __forceinline__ void mma_tf32(float c[4],
                                         uint32_t a0, uint32_t a1,
                                         uint32_t a2, uint32_t a3,
                                         uint32_t b0, uint32_t b1) {
    asm volatile(
        "mma.sync.aligned.m16n8k8.row.col.f32.tf32.tf32.f32 "
        "{%0,%1,%2,%3}, {%4,%5,%6,%7}, {%8,%9}, {%0,%1,%2,%3};"
        : "+f"(c[0]), "+f"(c[1]), "+f"(c[2]), "+f"(c[3])
        : "r"(a0), "r"(a1), "r"(a2), "r"(a3), "r"(b0), "r"(b1));
}

__device__ __forceinline__ float fast_tanh(float x) {
    float ax = fabsf(x);
    float t = __expf(-2.0f * ax);
    float r = __fdividef(1.0f - t, 1.0f + t);
    return copysignf(r, x);
}

__device__ __forceinline__ uint32_t smem_u32(const void* p) {
    uint32_t a;
    asm("{ .reg .u64 t; cvta.to.shared.u64 t, %1; cvt.u32.u64 %0, t; }"
        : "=r"(a) : "l"(p));
    return a;
}

#define CP_ASYNC(dst, src) \
    asm volatile("cp.async.cg.shared.global [%0], [%1], 16;" \
                 :: "r"(dst), "l"(src) : "memory")
#define CP_COMMIT() asm volatile("cp.async.commit_group;" ::: "memory")
#define CP_WAIT1()  asm volatile("cp.async.wait_group 1;" ::: "memory")

// ---- W convert: k16-fused B-block layout (verified R11/R12) ----
__global__ void convert_W(const float* __restrict__ W, uint32_t* __restrict__ out)
{
    const int nquads = 10 * 1024 * 1024 / 4;
    for (int q = blockIdx.x * blockDim.x + threadIdx.x; q < nquads;
         q += gridDim.x * blockDim.x) {
        uint32_t blk  = (uint32_t)q >> 5;
        uint32_t lane = (uint32_t)q & 31;
        uint32_t slab = blk >> 13;
        uint32_t rem  = blk & 8191u;
        uint32_t nb = rem >> 6, kp = rem & 63u;
        uint32_t g = lane >> 2, tig = lane & 3;
        const float* s = W + (size_t)slab * 1048576u
                           + (size_t)(nb * 8 + g) * 1024u + kp * 16 + tig;
        uint4 v;
        v.x = f2tf32(s[0]);
        v.y = f2tf32(s[4]);
        v.z = f2tf32(s[8]);
        v.w = f2tf32(s[12]);
        *reinterpret_cast<uint4*>(out + (size_t)q * 4) = v;
    }
}

// ---- X convert: A-block layout (verified R7-R12) ----
__global__ void convert_X(const float* __restrict__ x, uint32_t* __restrict__ out)
{
    const int nquads = 1024 * 1024 / 4;
    for (int q = blockIdx.x * blockDim.x + threadIdx.x; q < nquads;
         q += gridDim.x * blockDim.x) {
        uint32_t blk  = (uint32_t)q >> 5;
        uint32_t lane = (uint32_t)q & 31;
        uint32_t rb = blk >> 7, kb = blk & 127u;
        uint32_t g = lane >> 2, tig = lane & 3;
        const float* s0 = x + (size_t)(rb * 16 + g) * 1024u + kb * 8 + tig;
        uint4 v;
        v.x = f2tf32(s0[0]);
        v.y = f2tf32(s0[8192]);
        v.z = f2tf32(s0[4]);
        v.w = f2tf32(s0[8192 + 4]);
        *reinterpret_cast<uint4*>(out + (size_t)q * 4) = v;
    }
}

__global__ __launch_bounds__(THREADS, 2)
void ode_step(const uint32_t* __restrict__ Atf,   // H tf32, A-block layout
              const uint32_t* __restrict__ Btf,   // W slab tf32, k16-fused layout
              const float*    __restrict__ Hfp,   // traj[n] fp32 row-major
              const float*    __restrict__ bk,
              float*          __restrict__ Hout,  // traj[n+1] fp32 row-major
              uint32_t*       __restrict__ Houttf)// next H tf32, A-block layout
{
    extern __shared__ uint32_t smem[];
    const uint32_t sbase = smem_u32(smem);

    const int tid  = threadIdx.x;
    const int wid  = tid >> 5;
    const int lane = tid & 31;
    const int g    = lane >> 2;
    const int tig  = lane & 3;
    const int wm   = wid & 1;        // 2 warp rows of 32
    const int wn   = (wid >> 1) & 1; // 2 warp cols of 32
    const int ks   = wid >> 2;       // k-split half
    const int bm   = blockIdx.y * BM;
    const int bn   = blockIdx.x * BN;
    const int rb0  = blockIdx.y * 4;  // A 16-row block base
    const int nb0  = blockIdx.x * 8;  // B 8-col block base

    // B stage loader: 1024 16B chunks / 256 threads = 4 each
    auto issueB = [&](int s, int slot) {
        const uint32_t sst = sbase + (uint32_t)(slot * B_WORDS) * 4u;
        const int kp0 = s * 4;
#pragma unroll
        for (int i = 0; i < 4; i++) {
            int c = tid + i * THREADS;
            int nbl = c >> 7, j = c & 127;
            const uint32_t* src = Btf + ((size_t)(nb0 + nbl) * 64 + kp0) * 128 + j * 4;
            CP_ASYNC(sst + (uint32_t)(nbl * 512 + j * 4) * 4u, src);
        }
    };

    float acc[2][4][4];
#pragma unroll
    for (int mt = 0; mt < 2; mt++)
#pragma unroll
        for (int nt = 0; nt < 4; nt++)
#pragma unroll
            for (int r = 0; r < 4; r++) acc[mt][nt][r] = 0.0f;

    uint32_t fa[4][2][4];   // depth-4 A register ring (global -> reg)
    uint4    fbp[2][4];     // B k16 pairs from smem

    const int jb  = ks * 4;   // A k8-round base within each stage for this warp
    const int kpb = ks * 2;   // B k16-pair base

    // A fragment load straight from global (fragment-block layout, coalesced)
    auto loadA_g = [&](int J, int p) {   // J = global k8 index 0..127
#pragma unroll
        for (int mt = 0; mt < 2; mt++) {
            uint4 v = __ldg(reinterpret_cast<const uint4*>(
                Atf + ((size_t)(rb0 + wm * 2 + mt) * 128 + J) * 128 + lane * 4));
            fa[p][mt][0] = v.x; fa[p][mt][1] = v.y;
            fa[p][mt][2] = v.z; fa[p][mt][3] = v.w;
        }
    };
    auto loadBpair = [&](const uint32_t* __restrict__ st, int kpl, int pr) {
#pragma unroll
        for (int nt = 0; nt < 4; nt++) {
            fbp[pr][nt] = *reinterpret_cast<const uint4*>(
                st + ((wn * 4 + nt) * 4 + kpl) * 128 + lane * 4);
        }
    };
    auto do_mma = [&](int p, int pr, int odd) {
#pragma unroll
        for (int mt = 0; mt < 2; mt++)
#pragma unroll
            for (int nt = 0; nt < 4; nt++) {
                uint32_t b0 = odd ? fbp[pr][nt].z : fbp[pr][nt].x;
                uint32_t b1 = odd ? fbp[pr][nt].w : fbp[pr][nt].y;
                mma_tf32(acc[mt][nt],
                         fa[p][mt][0], fa[p][mt][1], fa[p][mt][2], fa[p][mt][3],
                         b0, b1);
            }
    };

    // ---- prologue ----
    issueB(0, 0); CP_COMMIT();
    issueB(1, 1); CP_COMMIT();
    // A register ring: preload per-warp rounds t = 0,1,2  (J = jb + t, stage 0)
    loadA_g(jb + 0, 0);
    loadA_g(jb + 1, 1);
    loadA_g(jb + 2, 2);

    int slot = 0, nslot = 2;
    for (int s = 0; s < KITERS; s++) {
        CP_WAIT1();          // B stage s landed
        __syncthreads();

        const uint32_t* st = smem + slot * B_WORDS;
        loadBpair(st, kpb + 0, 0);

        if (s + 2 < KITERS) issueB(s + 2, nslot);
        CP_COMMIT();         // keep group counting exact

#pragma unroll
        for (int jj = 0; jj < 4; jj++) {
            const int t3 = s * 4 + jj + 3;          // per-warp round t+3
            if (t3 < 4 * KITERS) {
                const int J3 = (t3 >> 2) * 8 + jb + (t3 & 3);
                loadA_g(J3, (jj + 3) & 3);
            }
            if (jj == 1) loadBpair(st, kpb + 1, 1);
            do_mma(jj, jj >> 1, jj & 1);
        }

        slot = slot + 1 == STAGES ? 0 : slot + 1;
        nslot = nslot + 1 == STAGES ? 0 : nslot + 1;
    }

    // ---- k-split reduction (exchange buffer = ring slot 0, 16KB) ----
    __syncthreads();
    float* ex = reinterpret_cast<float*>(smem);
    const int p = wid & 3;
    if (ks == 0) {
#pragma unroll
        for (int mt = 0; mt < 2; mt++)
#pragma unroll
            for (int nh = 0; nh < 2; nh++) {
                int q = mt * 2 + nh;
                float4 v = { acc[mt][2 + nh][0], acc[mt][2 + nh][1],
                             acc[mt][2 + nh][2], acc[mt][2 + nh][3] };
                *reinterpret_cast<float4*>(ex + (p * 4 + q) * 128 + lane * 4) = v;
            }
    } else {
#pragma unroll
        for (int mt = 0; mt < 2; mt++)
#pragma unroll
            for (int nh = 0; nh < 2; nh++) {
                int q = mt * 2 + nh;
                float4 v = { acc[mt][nh][0], acc[mt][nh][1],
                             acc[mt][nh][2], acc[mt][nh][3] };
                *reinterpret_cast<float4*>(ex + 2048 + (p * 4 + q) * 128 + lane * 4) = v;
            }
    }
    __syncthreads();
    const int ntb = ks ? 2 : 0;
    const int exo = ks ? 0 : 2048;
#pragma unroll
    for (int mt = 0; mt < 2; mt++)
#pragma unroll
        for (int nh = 0; nh < 2; nh++) {
            int q = mt * 2 + nh;
            float4 v = *reinterpret_cast<const float4*>(
                ex + exo + (p * 4 + q) * 128 + lane * 4);
            acc[mt][ntb + nh][0] += v.x;
            acc[mt][ntb + nh][1] += v.y;
            acc[mt][ntb + nh][2] += v.z;
            acc[mt][ntb + nh][3] += v.w;
        }

    // ---- fused epilogue (verified R7-R12) ----
#pragma unroll
    for (int mt = 0; mt < 2; mt++) {
#pragma unroll
        for (int nh = 0; nh < 2; nh++) {
            const int nt = ntb + nh;
            const int R = bm + wm * 32 + mt * 16 + g;
            const int C = bn + wn * 32 + nt * 8 + tig * 2;
            const float b0 = __ldg(&bk[C]);
            const float b1 = __ldg(&bk[C + 1]);

            float2 h0 = *reinterpret_cast<const float2*>(&Hfp[(size_t)R * D_DIM + C]);
            float2 h1 = *reinterpret_cast<const float2*>(&Hfp[(size_t)(R + 8) * D_DIM + C]);
            float o0 = h0.x + 0.1f * fast_tanh(acc[mt][nt][0] + b0);
            float o1 = h0.y + 0.1f * fast_tanh(acc[mt][nt][1] + b1);
            float o2 = h1.x + 0.1f * fast_tanh(acc[mt][nt][2] + b0);
            float o3 = h1.y + 0.1f * fast_tanh(acc[mt][nt][3] + b1);
            *reinterpret_cast<float2*>(&Hout[(size_t)R * D_DIM + C]) = make_float2(o0, o1);
            *reinterpret_cast<float2*>(&Hout[(size_t)(R + 8) * D_DIM + C]) = make_float2(o2, o3);

            const int rb = R >> 4, kb = C >> 3;
            const int t2 = tig * 2;
            const int kw = t2 >> 2;
            const int lane0 = g * 4 + (t2 & 3);
            const int lane1 = g * 4 + ((t2 + 1) & 3);
            uint32_t* base = Houttf + ((size_t)rb * 128 + kb) * 128 + 2 * kw;
            uint2 u02 = { f2tf32(o0), f2tf32(o2) };
            uint2 u13 = { f2tf32(o1), f2tf32(o3) };
            *reinterpret_cast<uint2*>(base + lane0 * 4) = u02;
            *reinterpret_cast<uint2*>(base + lane1 * 4) = u13;
        }
    }
}

extern "C" void kernel_launch(void* const* d_in, const int* in_sizes, int n_in,
                              void* d_out, int out_size)
{
    (void)in_sizes; (void)n_in; (void)out_size;
    const float* x = (const float*)d_in[0];   // [1024, 1024]
    const float* W = (const float*)d_in[1];   // [10, 1024, 1024]
    const float* b = (const float*)d_in[2];   // [10, 1024]

    float* out  = (float*)d_out;
    const size_t BD = (size_t)D_DIM * D_DIM;
    float* feat = out;
    float* traj = out + BD;

    uint32_t *wtf = nullptr, *htf = nullptr;
    cudaGetSymbolAddress((void**)&wtf, g_Wtf);
    cudaGetSymbolAddress((void**)&htf, g_Htf);
    uint32_t* htf0 = htf;
    uint32_t* htf1 = htf + BD;

    cudaFuncSetAttribute(ode_step,
                         cudaFuncAttributeMaxDynamicSharedMemorySize, SMEM_BYTES);

    convert_W<<<4096, 256>>>(W, wtf);
    convert_X<<<1024, 256>>>(x, htf0);
    cudaMemcpyAsync(traj, x, BD * sizeof(float), cudaMemcpyDeviceToDevice, 0);

    dim3 grid(D_DIM / BN, D_DIM / BM);   // (16, 16) = 256 CTAs
    dim3 block(THREADS);

    for (int n = 0; n < 100; n++) {
        int k = n / 10;
        uint32_t* hin  = (n & 1) ? htf1 : htf0;
        uint32_t* hnew = (n & 1) ? htf0 : htf1;
        ode_step<<<grid, block, SMEM_BYTES, 0>>>(
            hin,
            wtf + (size_t)k * BD,
            traj + (size_t)n * BD,
            b + (size_t)k * D_DIM,
            traj + (size_t)(n + 1) * BD,
            hnew);
    }

    cudaMemcpyAsync(feat, traj + (size_t)100 * BD, BD * sizeof(float),
                    cudaMemcpyDeviceToDevice, 0);
}

// round 14
// speedup vs baseline: 1.6630x; 1.6620x over previous
#include <cuda_runtime.h>
#include <cuda_fp16.h>
#include <cstdint>
#include <math.h>

// NeuralODE via mma.sync m16n8k16 FP16 (same 10-bit mantissa as tf32 -> same
// accuracy, half the instructions and half the bytes).
// h_{n+1} = h_n + 0.1 * tanh(h_n @ W[k]^T + b[k]), k = n/10, n = 0..99, B=D=1024.
// R14: CTA 64x64, 256 thr (2m x 2n x 2k), 3-stage cp.async ring (48KB), 2 CTAs/SM.
// Operands in fp16 fragment-block layouts; fp32 accum; fp32 traj recurrence.

#define D_DIM   1024
#define BM      64
#define BN      64
#define THREADS 256
#define KITERS  16
#define STAGES  3

#define A_WORDS 2048                 // 64 rows x 64 k fp16 = 8KB
#define B_WORDS 2048                 // 64 n x 64 k fp16 = 8KB
#define STAGE_WORDS (A_WORDS + B_WORDS)      // 4096
#define SMEM_BYTES (STAGES * STAGE_WORDS * 4)  // 49152

__device__ uint32_t g_Wh[10u * 512u * 1024u];   // W fp16, k32-fused B-block layout
__device__ uint32_t g_Hh[2][512u * 1024u];      // H fp16 ping-pong, A-block layout

__device__ __forceinline__ uint32_t pack2(float a, float b) {
    __half2 h = __floats2half2_rn(a, b);
    return *reinterpret_cast<uint32_t*>(&h);
}

__device__ __forceinline__ void mma_f16(float c[4],
                                        uint32_t a0, uint32_t a1,
                                        uint32_t a2, uint32_t a3,
                                        uint32_t b0, uint32_t b1) {
    asm volatile(
        "mma.sync.aligned.m16n8k16.row.col.f32.f16.f16.f32 "
        "{%0,%1,%2,%3}, {%4,%5,%6,%7}, {%8,%9}, {%0,%1,%2,%3};"
        : "+f"(c[0]), "+f"(c[1]), "+f"(c[2]), "+f"(c[3])
        : "r"(a0), "r"(a1), "r"(a2), "r"(a3), "r"(b0), "r"(b1));
}

__device__ __forceinline__ float fast_tanh(float x) {
    float ax = fabsf(x);
    float t = __expf(-2.0f * ax);
    float r = __fdividef(1.0f - t, 1.0f + t);
    return copysignf(r, x);
}

__device__ __forceinline__ uint32_t smem_u32(const void* p) {
    uint32_t a;
    asm("{ .reg .u64 t; cvta.to.shared.u64 t, %1; cvt.u32.u64 %0, t; }"
        : "=r"(a) : "l"(p));
    return a;
}

#define CP_ASYNC(dst, src) \
    asm volatile("cp.async.cg.shared.global [%0], [%1], 16;" \
                 :: "r"(dst), "l"(src) : "memory")
#define CP_COMMIT() asm volatile("cp.async.commit_group;" ::: "memory")
#define CP_WAIT1()  asm volatile("cp.async.wait_group 1;" ::: "memory")

// ---- W convert: fp16 k32-fused B-block layout ----
// block (slab, nb 0..127, kq 0..31): 128 words at ((slab*128+nb)*32+kq)*128.
// lane (g,tig) quad: { pack(W[n][K+2t],W[n][K+2t+1]),   pack(W[n][K+2t+8],+9),
//                      pack(W[n][K+16+2t],+1),          pack(W[n][K+24+2t],+1) }
// with n = nb*8+g, K = kq*32, t = tig. (words 0,1 = round even; 2,3 = round odd)
__global__ void convert_W(const float* __restrict__ W, uint32_t* __restrict__ out)
{
    const int nquads = 10 * 512 * 1024 / 4;   // 1310720
    for (int q = blockIdx.x * blockDim.x + threadIdx.x; q < nquads;
         q += gridDim.x * blockDim.x) {
        uint32_t blk  = (uint32_t)q >> 5;
        uint32_t lane = (uint32_t)q & 31;
        uint32_t slab = blk >> 12;          // 4096 blocks per slab
        uint32_t rem  = blk & 4095u;
        uint32_t nb = rem >> 5, kq = rem & 31u;
        uint32_t g = lane >> 2, tig = lane & 3;
        const float* s = W + (size_t)slab * 1048576u
                           + (size_t)(nb * 8 + g) * 1024u + kq * 32 + tig * 2;
        uint4 v;
        v.x = pack2(s[0],  s[1]);
        v.y = pack2(s[8],  s[9]);
        v.z = pack2(s[16], s[17]);
        v.w = pack2(s[24], s[25]);
        *reinterpret_cast<uint4*>(out + (size_t)q * 4) = v;
    }
}

// ---- X convert: fp16 A-block layout ----
// block (rb 0..63, kb16 0..63): 128 words at (rb*64+kb16)*128.
// lane (g,tig) quad: { pack(x[r][c],x[r][c+1]), pack(x[r+8][c],[c+1]),
//                      pack(x[r][c+8],[c+9]),   pack(x[r+8][c+8],[c+9]) }
// r = rb*16+g, c = kb16*16 + 2*tig.
__global__ void convert_X(const float* __restrict__ x, uint32_t* __restrict__ out)
{
    const int nquads = 512 * 1024 / 4;   // 131072
    for (int q = blockIdx.x * blockDim.x + threadIdx.x; q < nquads;
         q += gridDim.x * blockDim.x) {
        uint32_t blk  = (uint32_t)q >> 5;
        uint32_t lane = (uint32_t)q & 31;
        uint32_t rb = blk >> 6, kb = blk & 63u;
        uint32_t g = lane >> 2, tig = lane & 3;
        const float* s = x + (size_t)(rb * 16 + g) * 1024u + kb * 16 + tig * 2;
        uint4 v;
        v.x = pack2(s[0],        s[1]);
        v.y = pack2(s[8192],     s[8193]);     // row + 8
        v.z = pack2(s[8],        s[9]);
        v.w = pack2(s[8192 + 8], s[8192 + 9]);
        *reinterpret_cast<uint4*>(out + (size_t)q * 4) = v;
    }
}

__global__ __launch_bounds__(THREADS, 2)
void ode_step(const uint32_t* __restrict__ Ah,    // H fp16, A-block layout
              const uint32_t* __restrict__ Bh,    // W slab fp16, k32-fused layout
              const float*    __restrict__ Hfp,   // traj[n] fp32 row-major
              const float*    __restrict__ bk,
              float*          __restrict__ Hout,  // traj[n+1] fp32 row-major
              uint32_t*       __restrict__ Houth) // next H fp16, A-block layout
{
    extern __shared__ uint32_t smem[];
    const uint32_t sbase = smem_u32(smem);

    const int tid  = threadIdx.x;
    const int wid  = tid >> 5;
    const int lane = tid & 31;
    const int g    = lane >> 2;
    const int tig  = lane & 3;
    const int wm   = wid & 1;        // 2 warp rows of 32
    const int wn   = (wid >> 1) & 1; // 2 warp cols of 32
    const int ks   = wid >> 2;       // k-split half
    const int bm   = blockIdx.y * BM;
    const int bn   = blockIdx.x * BN;
    const int rb0  = blockIdx.y * 4;  // A 16-row block base
    const int nb0  = blockIdx.x * 8;  // B 8-col block base

    // stage s covers k in [s*64, s*64+64): A kb16 = s*4..s*4+3, B kq = s*2..s*2+1
    auto issueA = [&](int s, int slot) {
        const uint32_t sst = sbase + (uint32_t)(slot * STAGE_WORDS) * 4u;
#pragma unroll
        for (int i = 0; i < 2; i++) {           // 512 chunks / 256 thr
            int c = tid + i * THREADS;
            int rbl = c >> 7, j = c & 127;      // 4 kb16 x 128 words per rbl
            const uint32_t* src = Ah + ((size_t)(rb0 + rbl) * 64 + s * 4) * 128 + j * 4;
            CP_ASYNC(sst + (uint32_t)(rbl * 512 + j * 4) * 4u, src);
        }
    };
    auto issueB = [&](int s, int slot) {
        const uint32_t sst = sbase + (uint32_t)(slot * STAGE_WORDS) * 4u;
#pragma unroll
        for (int i = 0; i < 2; i++) {           // 512 chunks / 256 thr
            int c = tid + i * THREADS;
            int nbl = c >> 6, j = c & 63;       // 2 kq x 128 words per nbl
            const uint32_t* src = Bh + ((size_t)(nb0 + nbl) * 32 + s * 2) * 128 + j * 4;
            CP_ASYNC(sst + (uint32_t)(A_WORDS + nbl * 256 + j * 4) * 4u, src);
        }
    };

    float acc[2][4][4];
#pragma unroll
    for (int mt = 0; mt < 2; mt++)
#pragma unroll
        for (int nt = 0; nt < 4; nt++)
#pragma unroll
            for (int r = 0; r < 4; r++) acc[mt][nt][r] = 0.0f;

    uint32_t fa[2][2][4];   // [round buf][mt][a0..a3]
    uint4    fbp[4];        // [nt] = {b0_r0, b1_r0, b0_r1, b1_r1}

    auto loadA = [&](const uint32_t* __restrict__ st, int jl, int p) {
#pragma unroll
        for (int mt = 0; mt < 2; mt++) {
            uint4 v = *reinterpret_cast<const uint4*>(
                st + ((wm * 2 + mt) * 4 + jl) * 128 + lane * 4);
            fa[p][mt][0] = v.x; fa[p][mt][1] = v.y;
            fa[p][mt][2] = v.z; fa[p][mt][3] = v.w;
        }
    };
    auto loadB = [&](const uint32_t* __restrict__ st) {
#pragma unroll
        for (int nt = 0; nt < 4; nt++) {
            fbp[nt] = *reinterpret_cast<const uint4*>(
                st + A_WORDS + ((wn * 4 + nt) * 2 + ks) * 128 + lane * 4);
        }
    };
    auto do_mma = [&](int p, int r) {
#pragma unroll
        for (int mt = 0; mt < 2; mt++)
#pragma unroll
            for (int nt = 0; nt < 4; nt++) {
                uint32_t b0 = r ? fbp[nt].z : fbp[nt].x;
                uint32_t b1 = r ? fbp[nt].w : fbp[nt].y;
                mma_f16(acc[mt][nt],
                        fa[p][mt][0], fa[p][mt][1], fa[p][mt][2], fa[p][mt][3],
                        b0, b1);
            }
    };

    // ---- prologue ----
    issueA(0, 0); issueB(0, 0); CP_COMMIT();
    issueA(1, 1); issueB(1, 1); CP_COMMIT();

    const int jl0 = ks * 2;   // this warp's kb16-local base
    int slot = 0, nslot = 2;
    for (int s = 0; s < KITERS; s++) {
        CP_WAIT1();
        __syncthreads();

        const uint32_t* st = smem + slot * STAGE_WORDS;
        loadA(st, jl0 + 0, 0);
        loadB(st);

        if (s + 2 < KITERS) { issueA(s + 2, nslot); issueB(s + 2, nslot); }
        CP_COMMIT();

        loadA(st, jl0 + 1, 1);
        do_mma(0, 0);
        do_mma(1, 1);

        slot = slot + 1 == STAGES ? 0 : slot + 1;
        nslot = nslot + 1 == STAGES ? 0 : nslot + 1;
    }

    // ---- k-split reduction (exchange buffer = 16KB at smem base) ----
    __syncthreads();
    float* ex = reinterpret_cast<float*>(smem);
    const int p = wid & 3;
    if (ks == 0) {
#pragma unroll
        for (int mt = 0; mt < 2; mt++)
#pragma unroll
            for (int nh = 0; nh < 2; nh++) {
                int q = mt * 2 + nh;
                float4 v = { acc[mt][2 + nh][0], acc[mt][2 + nh][1],
                             acc[mt][2 + nh][2], acc[mt][2 + nh][3] };
                *reinterpret_cast<float4*>(ex + (p * 4 + q) * 128 + lane * 4) = v;
            }
    } else {
#pragma unroll
        for (int mt = 0; mt < 2; mt++)
#pragma unroll
            for (int nh = 0; nh < 2; nh++) {
                int q = mt * 2 + nh;
                float4 v = { acc[mt][nh][0], acc[mt][nh][1],
                             acc[mt][nh][2], acc[mt][nh][3] };
                *reinterpret_cast<float4*>(ex + 2048 + (p * 4 + q) * 128 + lane * 4) = v;
            }
    }
    __syncthreads();
    const int ntb = ks ? 2 : 0;
    const int exo = ks ? 0 : 2048;
#pragma unroll
    for (int mt = 0; mt < 2; mt++)
#pragma unroll
        for (int nh = 0; nh < 2; nh++) {
            int q = mt * 2 + nh;
            float4 v = *reinterpret_cast<const float4*>(
                ex + exo + (p * 4 + q) * 128 + lane * 4);
            acc[mt][ntb + nh][0] += v.x;
            acc[mt][ntb + nh][1] += v.y;
            acc[mt][ntb + nh][2] += v.z;
            acc[mt][ntb + nh][3] += v.w;
        }

    // ---- fused epilogue: fp32 traj + packed fp16 scatter into A-block layout ----
#pragma unroll
    for (int mt = 0; mt < 2; mt++) {
#pragma unroll
        for (int nh = 0; nh < 2; nh++) {
            const int nt = ntb + nh;
            const int R = bm + wm * 32 + mt * 16 + g;
            const int C = bn + wn * 32 + nt * 8 + tig * 2;
            const float b0 = __ldg(&bk[C]);
            const float b1 = __ldg(&bk[C + 1]);

            float2 h0 = *reinterpret_cast<const float2*>(&Hfp[(size_t)R * D_DIM + C]);
            float2 h1 = *reinterpret_cast<const float2*>(&Hfp[(size_t)(R + 8) * D_DIM + C]);
            float o0 = h0.x + 0.1f * fast_tanh(acc[mt][nt][0] + b0);
            float o1 = h0.y + 0.1f * fast_tanh(acc[mt][nt][1] + b1);
            float o2 = h1.x + 0.1f * fast_tanh(acc[mt][nt][2] + b0);
            float o3 = h1.y + 0.1f * fast_tanh(acc[mt][nt][3] + b1);
            *reinterpret_cast<float2*>(&Hout[(size_t)R * D_DIM + C]) = make_float2(o0, o1);
            *reinterpret_cast<float2*>(&Hout[(size_t)(R + 8) * D_DIM + C]) = make_float2(o2, o3);

            // scatter into fp16 A-block layout:
            // block (rb = R>>4, kb16 = C>>4); c2 = (C&15)>>1 = (nt&1)*4 + tig
            // c2<4 -> words 0,1 at lane (g, c2); c2>=4 -> words 2,3 at lane (g, c2-4)
            const int rb = R >> 4, kb = C >> 4;
            const int c2 = ((nt & 1) << 2) + tig;
            const int lt = g * 4 + (c2 & 3);
            const int wo = (c2 >= 4) ? 2 : 0;
            uint32_t* base = Houth + ((size_t)rb * 64 + kb) * 128 + lt * 4 + wo;
            uint2 u = { pack2(o0, o1), pack2(o2, o3) };
            *reinterpret_cast<uint2*>(base) = u;
        }
    }
}

extern "C" void kernel_launch(void* const* d_in, const int* in_sizes, int n_in,
                              void* d_out, int out_size)
{
    (void)in_sizes; (void)n_in; (void)out_size;
    const float* x = (const float*)d_in[0];   // [1024, 1024]
    const float* W = (const float*)d_in[1];   // [10, 1024, 1024]
    const float* b = (const float*)d_in[2];   // [10, 1024]

    float* out  = (float*)d_out;
    const size_t BD  = (size_t)D_DIM * D_DIM;
    const size_t BDH = BD / 2;                 // fp16 word count
    float* feat = out;
    float* traj = out + BD;

    uint32_t *wh = nullptr, *hh = nullptr;
    cudaGetSymbolAddress((void**)&wh, g_Wh);
    cudaGetSymbolAddress((void**)&hh, g_Hh);
    uint32_t* hh0 = hh;
    uint32_t* hh1 = hh + BDH;

    cudaFuncSetAttribute(ode_step,
                         cudaFuncAttributeMaxDynamicSharedMemorySize, SMEM_BYTES);

    convert_W<<<4096, 256>>>(W, wh);
    convert_X<<<1024, 256>>>(x, hh0);
    cudaMemcpyAsync(traj, x, BD * sizeof(float), cudaMemcpyDeviceToDevice, 0);

    dim3 grid(D_DIM / BN, D_DIM / BM);   // (16, 16) = 256 CTAs
    dim3 block(THREADS);

    for (int n = 0; n < 100; n++) {
        int k = n / 10;
        uint32_t* hin  = (n & 1) ? hh1 : hh0;
        uint32_t* hnew = (n & 1) ? hh0 : hh1;
        ode_step<<<grid, block, SMEM_BYTES, 0>>>(
            hin,
            wh + (size_t)k * BDH,
            traj + (size_t)n * BD,
            b + (size_t)k * D_DIM,
            traj + (size_t)(n + 1) * BD,
            hnew);
    }

    cudaMemcpyAsync(feat, traj + (size_t)100 * BD, BD * sizeof(float),
                    cudaMemcpyDeviceToDevice, 0);
}

// round 15
// speedup vs baseline: 1.7252x; 1.0374x over previous
#include <cuda_runtime.h>
#include <cuda_fp16.h>
#include <cstdint>
#include <math.h>

// NeuralODE via mma.sync m16n8k16 FP16, cp.async ring, fragment-block layouts.
// h_{n+1} = h_n + 0.1 * tanh(h_n @ W[k]^T + b[k]), k = n/10, n = 0..99, B=D=1024.
// R15: BK=128 per ring stage (KITERS=8) -> half the per-step syncs of R14.
// CTA 64x64, 256 thr (2m x 2n x 2k), 3-stage ring (96KB), 2 CTAs/SM, grid 256.

#define D_DIM   1024
#define BM      64
#define BN      64
#define THREADS 256
#define KITERS  8
#define STAGES  3

#define A_WORDS 4096                 // 64 rows x 128 k fp16 = 16KB
#define B_WORDS 4096                 // 64 n x 128 k fp16 = 16KB
#define STAGE_WORDS (A_WORDS + B_WORDS)      // 8192
#define SMEM_BYTES (STAGES * STAGE_WORDS * 4)  // 98304

__device__ uint32_t g_Wh[10u * 512u * 1024u];   // W fp16, k32-fused B-block layout
__device__ uint32_t g_Hh[2][512u * 1024u];      // H fp16 ping-pong, A-block layout

__device__ __forceinline__ uint32_t pack2(float a, float b) {
    __half2 h = __floats2half2_rn(a, b);
    return *reinterpret_cast<uint32_t*>(&h);
}

__device__ __forceinline__ void mma_f16(float c[4],
                                        uint32_t a0, uint32_t a1,
                                        uint32_t a2, uint32_t a3,
                                        uint32_t b0, uint32_t b1) {
    asm volatile(
        "mma.sync.aligned.m16n8k16.row.col.f32.f16.f16.f32 "
        "{%0,%1,%2,%3}, {%4,%5,%6,%7}, {%8,%9}, {%0,%1,%2,%3};"
        : "+f"(c[0]), "+f"(c[1]), "+f"(c[2]), "+f"(c[3])
        : "r"(a0), "r"(a1), "r"(a2), "r"(a3), "r"(b0), "r"(b1));
}

__device__ __forceinline__ float fast_tanh(float x) {
    float ax = fabsf(x);
    float t = __expf(-2.0f * ax);
    float r = __fdividef(1.0f - t, 1.0f + t);
    return copysignf(r, x);
}

__device__ __forceinline__ uint32_t smem_u32(const void* p) {
    uint32_t a;
    asm("{ .reg .u64 t; cvta.to.shared.u64 t, %1; cvt.u32.u64 %0, t; }"
        : "=r"(a) : "l"(p));
    return a;
}

#define CP_ASYNC(dst, src) \
    asm volatile("cp.async.cg.shared.global [%0], [%1], 16;" \
                 :: "r"(dst), "l"(src) : "memory")
#define CP_COMMIT() asm volatile("cp.async.commit_group;" ::: "memory")
#define CP_WAIT1()  asm volatile("cp.async.wait_group 1;" ::: "memory")

// ---- W convert: fp16 k32-fused B-block layout (verified R14) ----
__global__ void convert_W(const float* __restrict__ W, uint32_t* __restrict__ out)
{
    const int nquads = 10 * 512 * 1024 / 4;
    for (int q = blockIdx.x * blockDim.x + threadIdx.x; q < nquads;
         q += gridDim.x * blockDim.x) {
        uint32_t blk  = (uint32_t)q >> 5;
        uint32_t lane = (uint32_t)q & 31;
        uint32_t slab = blk >> 12;
        uint32_t rem  = blk & 4095u;
        uint32_t nb = rem >> 5, kq = rem & 31u;
        uint32_t g = lane >> 2, tig = lane & 3;
        const float* s = W + (size_t)slab * 1048576u
                           + (size_t)(nb * 8 + g) * 1024u + kq * 32 + tig * 2;
        uint4 v;
        v.x = pack2(s[0],  s[1]);
        v.y = pack2(s[8],  s[9]);
        v.z = pack2(s[16], s[17]);
        v.w = pack2(s[24], s[25]);
        *reinterpret_cast<uint4*>(out + (size_t)q * 4) = v;
    }
}

// ---- X convert: fp16 A-block layout (verified R14) ----
__global__ void convert_X(const float* __restrict__ x, uint32_t* __restrict__ out)
{
    const int nquads = 512 * 1024 / 4;
    for (int q = blockIdx.x * blockDim.x + threadIdx.x; q < nquads;
         q += gridDim.x * blockDim.x) {
        uint32_t blk  = (uint32_t)q >> 5;
        uint32_t lane = (uint32_t)q & 31;
        uint32_t rb = blk >> 6, kb = blk & 63u;
        uint32_t g = lane >> 2, tig = lane & 3;
        const float* s = x + (size_t)(rb * 16 + g) * 1024u + kb * 16 + tig * 2;
        uint4 v;
        v.x = pack2(s[0],        s[1]);
        v.y = pack2(s[8192],     s[8193]);
        v.z = pack2(s[8],        s[9]);
        v.w = pack2(s[8192 + 8], s[8192 + 9]);
        *reinterpret_cast<uint4*>(out + (size_t)q * 4) = v;
    }
}

__global__ __launch_bounds__(THREADS, 2)
void ode_step(const uint32_t* __restrict__ Ah,    // H fp16, A-block layout
              const uint32_t* __restrict__ Bh,    // W slab fp16, k32-fused layout
              const float*    __restrict__ Hfp,   // traj[n] fp32 row-major
              const float*    __restrict__ bk,
              float*          __restrict__ Hout,  // traj[n+1] fp32 row-major
              uint32_t*       __restrict__ Houth) // next H fp16, A-block layout
{
    extern __shared__ uint32_t smem[];
    const uint32_t sbase = smem_u32(smem);

    const int tid  = threadIdx.x;
    const int wid  = tid >> 5;
    const int lane = tid & 31;
    const int g    = lane >> 2;
    const int tig  = lane & 3;
    const int wm   = wid & 1;        // 2 warp rows of 32
    const int wn   = (wid >> 1) & 1; // 2 warp cols of 32
    const int ks   = wid >> 2;       // k-split half
    const int bm   = blockIdx.y * BM;
    const int bn   = blockIdx.x * BN;
    const int rb0  = blockIdx.y * 4;  // A 16-row block base
    const int nb0  = blockIdx.x * 8;  // B 8-col block base

    // stage s covers k in [s*128, s*128+128): A kb16 = s*8..+7, B kq = s*4..+3
    auto issueA = [&](int s, int slot) {
        const uint32_t sst = sbase + (uint32_t)(slot * STAGE_WORDS) * 4u;
#pragma unroll
        for (int i = 0; i < 4; i++) {           // 1024 chunks / 256 thr
            int c = tid + i * THREADS;
            int rbl = c >> 8, j = c & 255;      // 8 kb16 x 128 words per rbl
            const uint32_t* src = Ah + ((size_t)(rb0 + rbl) * 64 + s * 8) * 128 + j * 4;
            CP_ASYNC(sst + (uint32_t)(rbl * 1024 + j * 4) * 4u, src);
        }
    };
    auto issueB = [&](int s, int slot) {
        const uint32_t sst = sbase + (uint32_t)(slot * STAGE_WORDS) * 4u;
#pragma unroll
        for (int i = 0; i < 4; i++) {           // 1024 chunks / 256 thr
            int c = tid + i * THREADS;
            int nbl = c >> 7, j = c & 127;      // 4 kq x 128 words per nbl
            const uint32_t* src = Bh + ((size_t)(nb0 + nbl) * 32 + s * 4) * 128 + j * 4;
            CP_ASYNC(sst + (uint32_t)(A_WORDS + nbl * 512 + j * 4) * 4u, src);
        }
    };

    float acc[2][4][4];
#pragma unroll
    for (int mt = 0; mt < 2; mt++)
#pragma unroll
        for (int nt = 0; nt < 4; nt++)
#pragma unroll
            for (int r = 0; r < 4; r++) acc[mt][nt][r] = 0.0f;

    uint32_t fa[2][2][4];   // [buf][mt][a0..a3]
    uint4    fbp[2][4];     // [buf][nt] = {b0_r0, b1_r0, b0_r1, b1_r1}

    auto loadA = [&](const uint32_t* __restrict__ st, int jl, int p) {
#pragma unroll
        for (int mt = 0; mt < 2; mt++) {
            uint4 v = *reinterpret_cast<const uint4*>(
                st + ((wm * 2 + mt) * 8 + jl) * 128 + lane * 4);
            fa[p][mt][0] = v.x; fa[p][mt][1] = v.y;
            fa[p][mt][2] = v.z; fa[p][mt][3] = v.w;
        }
    };
    auto loadB = [&](const uint32_t* __restrict__ st, int kql, int pr) {
#pragma unroll
        for (int nt = 0; nt < 4; nt++) {
            fbp[pr][nt] = *reinterpret_cast<const uint4*>(
                st + A_WORDS + ((wn * 4 + nt) * 4 + kql) * 128 + lane * 4);
        }
    };
    auto do_mma = [&](int p, int pr, int r) {
#pragma unroll
        for (int mt = 0; mt < 2; mt++)
#pragma unroll
            for (int nt = 0; nt < 4; nt++) {
                uint32_t b0 = r ? fbp[pr][nt].z : fbp[pr][nt].x;
                uint32_t b1 = r ? fbp[pr][nt].w : fbp[pr][nt].y;
                mma_f16(acc[mt][nt],
                        fa[p][mt][0], fa[p][mt][1], fa[p][mt][2], fa[p][mt][3],
                        b0, b1);
            }
    };

    // ---- prologue ----
    issueA(0, 0); issueB(0, 0); CP_COMMIT();
    issueA(1, 1); issueB(1, 1); CP_COMMIT();

    const int jl0 = ks * 4;   // kb16-local base for this warp (8 per stage)
    const int kqb = ks * 2;   // kq-local base (4 per stage)
    int slot = 0, nslot = 2;
    for (int s = 0; s < KITERS; s++) {
        CP_WAIT1();
        __syncthreads();

        const uint32_t* st = smem + slot * STAGE_WORDS;

        loadA(st, jl0 + 0, 0);
        loadB(st, kqb + 0, 0);

        if (s + 2 < KITERS) { issueA(s + 2, nslot); issueB(s + 2, nslot); }
        CP_COMMIT();

        loadA(st, jl0 + 1, 1);
        do_mma(0, 0, 0);                 // kq0 round 0
        loadA(st, jl0 + 2, 0);
        loadB(st, kqb + 1, 1);
        do_mma(1, 0, 1);                 // kq0 round 1
        loadA(st, jl0 + 3, 1);
        do_mma(0, 1, 0);                 // kq1 round 0
        do_mma(1, 1, 1);                 // kq1 round 1

        slot = slot + 1 == STAGES ? 0 : slot + 1;
        nslot = nslot + 1 == STAGES ? 0 : nslot + 1;
    }

    // ---- k-split reduction (exchange buffer = 16KB at smem base) ----
    __syncthreads();
    float* ex = reinterpret_cast<float*>(smem);
    const int p = wid & 3;
    if (ks == 0) {
#pragma unroll
        for (int mt = 0; mt < 2; mt++)
#pragma unroll
            for (int nh = 0; nh < 2; nh++) {
                int q = mt * 2 + nh;
                float4 v = { acc[mt][2 + nh][0], acc[mt][2 + nh][1],
                             acc[mt][2 + nh][2], acc[mt][2 + nh][3] };
                *reinterpret_cast<float4*>(ex + (p * 4 + q) * 128 + lane * 4) = v;
            }
    } else {
#pragma unroll
        for (int mt = 0; mt < 2; mt++)
#pragma unroll
            for (int nh = 0; nh < 2; nh++) {
                int q = mt * 2 + nh;
                float4 v = { acc[mt][nh][0], acc[mt][nh][1],
                             acc[mt][nh][2], acc[mt][nh][3] };
                *reinterpret_cast<float4*>(ex + 2048 + (p * 4 + q) * 128 + lane * 4) = v;
            }
    }
    __syncthreads();
    const int ntb = ks ? 2 : 0;
    const int exo = ks ? 0 : 2048;
#pragma unroll
    for (int mt = 0; mt < 2; mt++)
#pragma unroll
        for (int nh = 0; nh < 2; nh++) {
            int q = mt * 2 + nh;
            float4 v = *reinterpret_cast<const float4*>(
                ex + exo + (p * 4 + q) * 128 + lane * 4);
            acc[mt][ntb + nh][0] += v.x;
            acc[mt][ntb + nh][1] += v.y;
            acc[mt][ntb + nh][2] += v.z;
            acc[mt][ntb + nh][3] += v.w;
        }

    // ---- fused epilogue: fp32 traj + packed fp16 scatter (verified R14) ----
#pragma unroll
    for (int mt = 0; mt < 2; mt++) {
#pragma unroll
        for (int nh = 0; nh < 2; nh++) {
            const int nt = ntb + nh;
            const int R = bm + wm * 32 + mt * 16 + g;
            const int C = bn + wn * 32 + nt * 8 + tig * 2;
            const float b0 = __ldg(&bk[C]);
            const float b1 = __ldg(&bk[C + 1]);

            float2 h0 = *reinterpret_cast<const float2*>(&Hfp[(size_t)R * D_DIM + C]);
            float2 h1 = *reinterpret_cast<const float2*>(&Hfp[(size_t)(R + 8) * D_DIM + C]);
            float o0 = h0.x + 0.1f * fast_tanh(acc[mt][nt][0] + b0);
            float o1 = h0.y + 0.1f * fast_tanh(acc[mt][nt][1] + b1);
            float o2 = h1.x + 0.1f * fast_tanh(acc[mt][nt][2] + b0);
            float o3 = h1.y + 0.1f * fast_tanh(acc[mt][nt][3] + b1);
            *reinterpret_cast<float2*>(&Hout[(size_t)R * D_DIM + C]) = make_float2(o0, o1);
            *reinterpret_cast<float2*>(&Hout[(size_t)(R + 8) * D_DIM + C]) = make_float2(o2, o3);

            const int rb = R >> 4, kb = C >> 4;
            const int c2 = ((nt & 1) << 2) + tig;
            const int lt = g * 4 + (c2 & 3);
            const int wo = (c2 >= 4) ? 2 : 0;
            uint32_t* base = Houth + ((size_t)rb * 64 + kb) * 128 + lt * 4 + wo;
            uint2 u = { pack2(o0, o1), pack2(o2, o3) };
            *reinterpret_cast<uint2*>(base) = u;
        }
    }
}

extern "C" void kernel_launch(void* const* d_in, const int* in_sizes, int n_in,
                              void* d_out, int out_size)
{
    (void)in_sizes; (void)n_in; (void)out_size;
    const float* x = (const float*)d_in[0];   // [1024, 1024]
    const float* W = (const float*)d_in[1];   // [10, 1024, 1024]
    const float* b = (const float*)d_in[2];   // [10, 1024]

    float* out  = (float*)d_out;
    const size_t BD  = (size_t)D_DIM * D_DIM;
    const size_t BDH = BD / 2;
    float* feat = out;
    float* traj = out + BD;

    uint32_t *wh = nullptr, *hh = nullptr;
    cudaGetSymbolAddress((void**)&wh, g_Wh);
    cudaGetSymbolAddress((void**)&hh, g_Hh);
    uint32_t* hh0 = hh;
    uint32_t* hh1 = hh + BDH;

    cudaFuncSetAttribute(ode_step,
                         cudaFuncAttributeMaxDynamicSharedMemorySize, SMEM_BYTES);

    convert_W<<<4096, 256>>>(W, wh);
    convert_X<<<1024, 256>>>(x, hh0);
    cudaMemcpyAsync(traj, x, BD * sizeof(float), cudaMemcpyDeviceToDevice, 0);

    dim3 grid(D_DIM / BN, D_DIM / BM);   // (16, 16) = 256 CTAs
    dim3 block(THREADS);

    for (int n = 0; n < 100; n++) {
        int k = n / 10;
        uint32_t* hin  = (n & 1) ? hh1 : hh0;
        uint32_t* hnew = (n & 1) ? hh0 : hh1;
        ode_step<<<grid, block, SMEM_BYTES, 0>>>(
            hin,
            wh + (size_t)k * BDH,
            traj + (size_t)n * BD,
            b + (size_t)k * D_DIM,
            traj + (size_t)(n + 1) * BD,
            hnew);
    }

    cudaMemcpyAsync(feat, traj + (size_t)100 * BD, BD * sizeof(float),
                    cudaMemcpyDeviceToDevice, 0);
}